// round 16
// baseline (speedup 1.0000x reference)
#include <cuda_runtime.h>
#include <cuda_fp16.h>
#include <cstdint>
#include <cstddef>

// Problem dims
#define BB   4
#define LL   4096
#define DIMM 2048
#define SS   128
#define MM   (BB*LL)        // 16384 token rows
#define N1   512            // dt | Bx_re | Bx_im | pg
#define K1   6144           // xr(2048) | xi(2048) | cab(2048)
#define K2   256            // hr(128) | hi(128)
#define N2   4096           // interleaved (yr,yi) per d
#define NC   64             // scan chunks per lane
#define CHUNK (LL/NC)       // 64

// SMEM staging: 128 rows x 32 k halves per stage, padded to 40 halves/row
// (80 B = 20 banks; (20r+t) mod 32 covers all banks -> conflict-free ldmatrix)
#define TPAD    40
#define TSTAGE  (128*TPAD*2)        // bytes per tile stage (10240)
#define STAGES  4
#define SMEM_BYTES (2*STAGES*TSTAGE) // A stages then B stages (81920)

// -------- scratch (__device__ globals; no allocations allowed) --------
__device__ __half g_Ah[(size_t)MM*K1];      // fp16 A operand: [xr|xi|cab] per row
__device__ __half g_W1h[(size_t)N1*K1];     // GEMM1 B operand, [n][k], fp16
__device__ __half g_W2h[(size_t)N2*K2];     // GEMM2 B operand, [n][k], fp16
__device__ float  g_G1[(size_t)MM*N1];      // GEMM1 fp32 outputs
__device__ float4 g_ABx[(size_t)MM*SS];     // {Ar,Ai,Bxr,Bxi} per (m,s)
__device__ float2 g_cA[BB*NC*SS];           // chunk A-products
__device__ float2 g_cH[BB*NC*SS];           // chunk local h_end
__device__ float2 g_carry[BB*NC*SS];        // per-chunk carry-in
__device__ __half g_Hh[(size_t)MM*K2];      // [hr|hi] rows, fp16, for GEMM2

__device__ __forceinline__ void mma16(float* c, const unsigned* a, const unsigned* b){
    asm volatile(
        "mma.sync.aligned.m16n8k16.row.col.f32.f16.f16.f32 "
        "{%0,%1,%2,%3}, {%4,%5,%6,%7}, {%8,%9}, {%0,%1,%2,%3};\n"
        : "+f"(c[0]), "+f"(c[1]), "+f"(c[2]), "+f"(c[3])
        : "r"(a[0]), "r"(a[1]), "r"(a[2]), "r"(a[3]), "r"(b[0]), "r"(b[1]));
}
__device__ __forceinline__ void ldsm4(unsigned& r0, unsigned& r1, unsigned& r2, unsigned& r3,
                                      uint32_t addr){
    asm volatile("ldmatrix.sync.aligned.m8n8.x4.shared.b16 {%0,%1,%2,%3}, [%4];"
        : "=r"(r0), "=r"(r1), "=r"(r2), "=r"(r3) : "r"(addr));
}
__device__ __forceinline__ uint32_t smem_u32(const void* p){
    uint32_t a;
    asm("{ .reg .u64 t; cvta.to.shared.u64 t, %1; cvt.u32.u64 %0, t; }" : "=r"(a) : "l"(p));
    return a;
}
#define CP16(dst, src) \
    asm volatile("cp.async.cg.shared.global [%0], [%1], 16;" :: "r"(dst), "l"(src))
#define CPCOMMIT() asm volatile("cp.async.commit_group;" ::: "memory")
#define CPWAIT2()  asm volatile("cp.async.wait_group 2;" ::: "memory")

extern __shared__ char smx[];

// ---------------- prep: fp16 A operand [xr | xi | cab] ----------------
__global__ void prep_ah(const float* __restrict__ x){
    size_t idx = (size_t)blockIdx.x*256 + threadIdx.x;   // over MM*DIMM
    size_t m = idx >> 11;
    int d = (int)(idx & 2047);
    float2 v = reinterpret_cast<const float2*>(x)[idx];
    __half* row = g_Ah + m*K1;
    row[d]        = __float2half_rn(v.x);
    row[2048 + d] = __float2half_rn(v.y);
    row[4096 + d] = __float2half_rn(sqrtf(v.x*v.x + v.y*v.y));
}

// ---------------- weight packing ([n][k] fp16) ----------------
__global__ void prep_w1h(const float* __restrict__ dt_w, const float* __restrict__ Br,
                         const float* __restrict__ Bi,   const float* __restrict__ pg_w){
    size_t idx = (size_t)blockIdx.x*256 + threadIdx.x;   // over N1*K1, k fast
    int n = (int)(idx / K1);
    int k = (int)(idx - (size_t)n*K1);
    float v = 0.f;
    if (n < 128) {
        if (k < 4096) v = dt_w[(size_t)n*4096 + k];
    } else if (n < 256) {
        int s = n - 128;
        if (k < 2048)       v =  Br[(size_t)k*SS + s];
        else if (k < 4096)  v = -Bi[(size_t)(k-2048)*SS + s];
    } else if (n < 384) {
        int s = n - 256;
        if (k < 2048)       v =  Bi[(size_t)k*SS + s];
        else if (k < 4096)  v =  Br[(size_t)(k-2048)*SS + s];
    } else {
        int s = n - 384;
        if (k >= 4096)      v =  pg_w[(size_t)s*DIMM + (k-4096)];
    }
    g_W1h[idx] = __float2half_rn(v);
}

__global__ void prep_w2h(const float* __restrict__ Cr, const float* __restrict__ Ci){
    size_t idx = (size_t)blockIdx.x*256 + threadIdx.x;   // over N2*K2, k fast
    int n = (int)(idx >> 8);
    int k = (int)(idx & 255);
    int d = n >> 1, c = n & 1;
    float v;
    if (k < 128) v = c ? Ci[(size_t)k*DIMM + d] : Cr[(size_t)k*DIMM + d];
    else { int s = k - 128; v = c ? Cr[(size_t)s*DIMM + d] : -Ci[(size_t)s*DIMM + d]; }
    g_W2h[idx] = __float2half_rn(v);
}

// ---------------- GEMM1: projections (4-stage cp.async + ldmatrix + HMMA) ----------------
// grid: blockIdx = mt*4 + nb; nb 0..2: K=[0,4096); nb==3: K=[4096,6144).
// 256 threads, 8 warps: warp tile 64m x 32n over 128x128 block tile.
__global__ __launch_bounds__(256,2) void gemm1(){
    const int tid = threadIdx.x, lane = tid & 31, warp = tid >> 5;
    const int nb = blockIdx.x & 3, mt = blockIdx.x >> 2;
    const int kstart = (nb < 3) ? 0 : 4096;
    const int KT     = (nb < 3) ? 128 : 64;
    const int wm = (warp & 1) * 64, wn = (warp >> 1) * 32;

    const uint32_t sb = smem_u32(smx);
    const int ldrow = tid >> 1, ldseg = (tid & 1);
    const __half* Ag = g_Ah  + (size_t)(mt*128 + ldrow)*K1 + kstart + ldseg*16;
    const __half* Bg = g_W1h + (size_t)(nb*128 + ldrow)*K1 + kstart + ldseg*16;
    const uint32_t dA = sb + ldrow*80 + ldseg*32;
    const uint32_t dB = dA + STAGES*TSTAGE;

    const int arow = (lane & 7) + ((lane >> 3) & 1) * 8;
    const int acol = (lane >> 4) * 8;
    const int brow = (lane & 7) + (lane >> 4) * 8;
    const int bcol = ((lane >> 3) & 1) * 8;
    const uint32_t aoff = sb + ((wm + arow)*TPAD + acol)*2;
    const uint32_t boff = sb + STAGES*TSTAGE + ((wn + brow)*TPAD + bcol)*2;

    float acc[4][4][4];
    #pragma unroll
    for (int mi=0;mi<4;mi++)
        #pragma unroll
        for (int ni=0;ni<4;ni++){ acc[mi][ni][0]=0.f; acc[mi][ni][1]=0.f; acc[mi][ni][2]=0.f; acc[mi][ni][3]=0.f; }

    auto ISSUE = [&](int kt, int st){
        const __half* a = Ag + kt*32;
        const __half* b = Bg + kt*32;
        const uint32_t da = dA + st*TSTAGE, db = dB + st*TSTAGE;
        CP16(da,      a);
        CP16(da + 16, a + 8);
        CP16(db,      b);
        CP16(db + 16, b + 8);
        CPCOMMIT();
    };
    auto COMPUTE = [&](int st){
        const uint32_t ab = aoff + st*TSTAGE;
        const uint32_t bb = boff + st*TSTAGE;
        #pragma unroll
        for (int ks=0; ks<2; ks++){
            const uint32_t kb2 = ks*32;   // 16 halves * 2B
            unsigned af[4][4], bf[2][4];
            #pragma unroll
            for (int mi=0;mi<4;mi++)
                ldsm4(af[mi][0],af[mi][1],af[mi][2],af[mi][3], ab + mi*16*80 + kb2);
            #pragma unroll
            for (int np=0;np<2;np++)
                ldsm4(bf[np][0],bf[np][1],bf[np][2],bf[np][3], bb + np*16*80 + kb2);
            #pragma unroll
            for (int mi=0;mi<4;mi++)
                #pragma unroll
                for (int ni=0;ni<4;ni++){
                    unsigned bx[2] = { bf[ni>>1][(ni&1)*2], bf[ni>>1][(ni&1)*2+1] };
                    mma16(acc[mi][ni], af[mi], bx);
                }
        }
    };

    #pragma unroll
    for (int s=0; s<STAGES-1; s++) ISSUE(s, s);
    for (int kt=0; kt<KT; kt++){
        CPWAIT2();
        __syncthreads();
        const int nx = kt + STAGES-1;
        if (nx < KT) ISSUE(nx, nx & (STAGES-1)); else CPCOMMIT();
        COMPUTE(kt & (STAGES-1));
    }

    const int g = lane >> 2, t = lane & 3;
    #pragma unroll
    for (int mi=0;mi<4;mi++){
        int row = mt*128 + wm + mi*16 + g;
        #pragma unroll
        for (int ni=0;ni<4;ni++){
            int col = nb*128 + wn + ni*8 + t*2;
            *reinterpret_cast<float2*>(&g_G1[(size_t)row*N1 + col])     = make_float2(acc[mi][ni][0], acc[mi][ni][1]);
            *reinterpret_cast<float2*>(&g_G1[(size_t)(row+8)*N1 + col]) = make_float2(acc[mi][ni][2], acc[mi][ni][3]);
        }
    }
}

// ---------------- elementwise: build A, Bx ----------------
__global__ void ew1(const float* __restrict__ dt_b, const float* __restrict__ dt_bias,
                    const float* __restrict__ lAr,  const float* __restrict__ lAi,
                    const float* __restrict__ pg_b){
    __shared__ float s_ear[SS], s_cos[SS], s_sin[SS], s_db[SS], s_pb[SS];
    int tid = threadIdx.x;
    if (tid < SS){
        s_ear[tid] = expf(lAr[tid]);
        float sn, cs; sincosf(lAi[tid], &sn, &cs);
        s_cos[tid]=cs; s_sin[tid]=sn;
        s_db[tid] = dt_b[tid] + dt_bias[tid];
        s_pb[tid] = pg_b[tid];
    }
    __syncthreads();
    size_t idx = (size_t)blockIdx.x*256 + tid;      // over MM*SS
    int s = (int)(idx & 127);
    size_t m = idx >> 7;
    const float* row = &g_G1[m*N1];
    float z  = row[s] + s_db[s];
    float dt = (z > 20.f) ? z : log1pf(expf(z));
    float bxr = row[128+s], bxi = row[256+s];
    float pz  = row[384+s] + s_pb[s];
    float p   = 1.f/(1.f+expf(-pz));
    float am  = expf(-dt * s_ear[s]);
    float omp = 1.f - p;
    float Ar = p + omp*am*s_cos[s];
    float Ai = omp*am*s_sin[s];
    float sc = omp*dt;
    g_ABx[idx] = make_float4(Ar, Ai, bxr*sc, bxi*sc);
}

// ---------------- chunked scan ----------------
__global__ void scan_a(){
    int b = blockIdx.x >> 6;
    int c = blockIdx.x & (NC-1);
    int s = threadIdx.x;
    size_t base = ((size_t)b*LL + (size_t)c*CHUNK)*SS + s;
    float hr=0.f, hi=0.f, pr=1.f, pi=0.f;
    #pragma unroll 4
    for (int i=0;i<CHUNK;i++){
        float4 v = g_ABx[base + (size_t)i*SS];
        float nhr = v.x*hr - v.y*hi + v.z;
        float nhi = v.x*hi + v.y*hr + v.w;
        float npr = v.x*pr - v.y*pi;
        float npi = v.x*pi + v.y*pr;
        hr=nhr; hi=nhi; pr=npr; pi=npi;
    }
    int o = (b*NC + c)*SS + s;
    g_cA[o] = make_float2(pr,pi);
    g_cH[o] = make_float2(hr,hi);
}

__global__ void scan_b(){
    int tid = threadIdx.x;            // 512 = BB*SS
    int b = tid >> 7, s = tid & 127;
    float cr=0.f, ci=0.f;
    for (int c=0;c<NC;c++){
        int o = (b*NC + c)*SS + s;
        g_carry[o] = make_float2(cr,ci);
        float2 a = g_cA[o]; float2 h = g_cH[o];
        float nr  = a.x*cr - a.y*ci + h.x;
        float ni2 = a.x*ci + a.y*cr + h.y;
        cr=nr; ci=ni2;
    }
}

__global__ void scan_c(float* __restrict__ out){
    int b = blockIdx.x >> 6;
    int c = blockIdx.x & (NC-1);
    int s = threadIdx.x;
    int o = (b*NC + c)*SS + s;
    float2 cc = g_carry[o];
    float hr = cc.x, hi = cc.y;
    size_t base  = ((size_t)b*LL + (size_t)c*CHUNK)*SS + s;
    size_t mbase = (size_t)b*LL + (size_t)c*CHUNK;
    for (int i=0;i<CHUNK;i++){
        float4 v = g_ABx[base + (size_t)i*SS];
        float nhr = v.x*hr - v.y*hi + v.z;
        float nhi = v.x*hi + v.y*hr + v.w;
        hr=nhr; hi=nhi;
        size_t m = mbase + i;
        g_Hh[m*K2 + s]       = __float2half_rn(hr);
        g_Hh[m*K2 + 128 + s] = __float2half_rn(hi);
    }
    if (c == NC-1){
        out[(size_t)MM*N2 + (b*SS + s)*2 + 0] = hr;
        out[(size_t)MM*N2 + (b*SS + s)*2 + 1] = hi;
    }
}

// ---------------- GEMM2: y = [hr|hi] @ W2 + cmul(D,x) ----------------
// grid: blockIdx = mt*32 + nt. 256 threads, 8 warps, warp tile 64x32.
__global__ __launch_bounds__(256,2) void gemm2(const float* __restrict__ x,
                                               const float* __restrict__ Dp,
                                               float* __restrict__ out){
    const int tid = threadIdx.x, lane = tid & 31, warp = tid >> 5;
    const int nt = blockIdx.x & 31, mt = blockIdx.x >> 5;
    const int KT = K2/32;   // 8
    const int wm = (warp & 1) * 64, wn = (warp >> 1) * 32;

    const uint32_t sb = smem_u32(smx);
    const int ldrow = tid >> 1, ldseg = (tid & 1);
    const __half* Ag = g_Hh  + (size_t)(mt*128 + ldrow)*K2 + ldseg*16;
    const __half* Bg = g_W2h + (size_t)(nt*128 + ldrow)*K2 + ldseg*16;
    const uint32_t dA = sb + ldrow*80 + ldseg*32;
    const uint32_t dB = dA + STAGES*TSTAGE;

    const int arow = (lane & 7) + ((lane >> 3) & 1) * 8;
    const int acol = (lane >> 4) * 8;
    const int brow = (lane & 7) + (lane >> 4) * 8;
    const int bcol = ((lane >> 3) & 1) * 8;
    const uint32_t aoff = sb + ((wm + arow)*TPAD + acol)*2;
    const uint32_t boff = sb + STAGES*TSTAGE + ((wn + brow)*TPAD + bcol)*2;

    float acc[4][4][4];
    #pragma unroll
    for (int mi=0;mi<4;mi++)
        #pragma unroll
        for (int ni=0;ni<4;ni++){ acc[mi][ni][0]=0.f; acc[mi][ni][1]=0.f; acc[mi][ni][2]=0.f; acc[mi][ni][3]=0.f; }

    auto ISSUE = [&](int kt, int st){
        const __half* a = Ag + kt*32;
        const __half* b = Bg + kt*32;
        const uint32_t da = dA + st*TSTAGE, db = dB + st*TSTAGE;
        CP16(da,      a);
        CP16(da + 16, a + 8);
        CP16(db,      b);
        CP16(db + 16, b + 8);
        CPCOMMIT();
    };
    auto COMPUTE = [&](int st){
        const uint32_t ab = aoff + st*TSTAGE;
        const uint32_t bb = boff + st*TSTAGE;
        #pragma unroll
        for (int ks=0; ks<2; ks++){
            const uint32_t kb2 = ks*32;
            unsigned af[4][4], bf[2][4];
            #pragma unroll
            for (int mi=0;mi<4;mi++)
                ldsm4(af[mi][0],af[mi][1],af[mi][2],af[mi][3], ab + mi*16*80 + kb2);
            #pragma unroll
            for (int np=0;np<2;np++)
                ldsm4(bf[np][0],bf[np][1],bf[np][2],bf[np][3], bb + np*16*80 + kb2);
            #pragma unroll
            for (int mi=0;mi<4;mi++)
                #pragma unroll
                for (int ni=0;ni<4;ni++){
                    unsigned bx[2] = { bf[ni>>1][(ni&1)*2], bf[ni>>1][(ni&1)*2+1] };
                    mma16(acc[mi][ni], af[mi], bx);
                }
        }
    };

    #pragma unroll
    for (int s=0; s<STAGES-1; s++) ISSUE(s, s);
    for (int kt=0; kt<KT; kt++){
        CPWAIT2();
        __syncthreads();
        const int nx = kt + STAGES-1;
        if (nx < KT) ISSUE(nx, nx & (STAGES-1)); else CPCOMMIT();
        COMPUTE(kt & (STAGES-1));
    }

    const int g = lane >> 2, t = lane & 3;
    #pragma unroll
    for (int mi=0;mi<4;mi++){
        int row = mt*128 + wm + mi*16 + g;
        #pragma unroll
        for (int ni=0;ni<4;ni++){
            int ncol = nt*128 + wn + ni*8 + t*2;   // even
            int d = ncol >> 1;
            float2 Dv  = *reinterpret_cast<const float2*>(&Dp[d*2]);
            float2 xv0 = *reinterpret_cast<const float2*>(&x[((size_t)row*DIMM + d)*2]);
            float2 xv1 = *reinterpret_cast<const float2*>(&x[((size_t)(row+8)*DIMM + d)*2]);
            float y00 = acc[mi][ni][0] + Dv.x*xv0.x - Dv.y*xv0.y;
            float y01 = acc[mi][ni][1] + Dv.x*xv0.y + Dv.y*xv0.x;
            float y10 = acc[mi][ni][2] + Dv.x*xv1.x - Dv.y*xv1.y;
            float y11 = acc[mi][ni][3] + Dv.x*xv1.y + Dv.y*xv1.x;
            *reinterpret_cast<float2*>(&out[(size_t)row*N2 + ncol])     = make_float2(y00,y01);
            *reinterpret_cast<float2*>(&out[(size_t)(row+8)*N2 + ncol]) = make_float2(y10,y11);
        }
    }
}

// ---------------- launch ----------------
extern "C" void kernel_launch(void* const* d_in, const int* in_sizes, int n_in,
                              void* d_out, int out_size){
    const float* x       = (const float*)d_in[0];
    const float* lAr     = (const float*)d_in[1];
    const float* lAi     = (const float*)d_in[2];
    const float* Dp      = (const float*)d_in[3];
    const float* dt_w    = (const float*)d_in[4];
    const float* dt_b    = (const float*)d_in[5];
    const float* dt_bias = (const float*)d_in[6];
    const float* Br      = (const float*)d_in[7];
    const float* Bi      = (const float*)d_in[8];
    const float* Cr      = (const float*)d_in[9];
    const float* Ci      = (const float*)d_in[10];
    const float* pg_w    = (const float*)d_in[11];
    const float* pg_b    = (const float*)d_in[12];
    float* out = (float*)d_out;

    cudaFuncSetAttribute(gemm1, cudaFuncAttributeMaxDynamicSharedMemorySize, SMEM_BYTES);
    cudaFuncSetAttribute(gemm2, cudaFuncAttributeMaxDynamicSharedMemorySize, SMEM_BYTES);

    prep_ah<<<(int)(((size_t)MM*DIMM)/256), 256>>>(x);
    prep_w1h<<<(int)(((size_t)N1*K1)/256), 256>>>(dt_w, Br, Bi, pg_w);
    prep_w2h<<<(int)(((size_t)N2*K2)/256), 256>>>(Cr, Ci);
    gemm1<<<(MM/128)*4, 256, SMEM_BYTES>>>();
    ew1<<<(MM*SS)/256, 256>>>(dt_b, dt_bias, lAr, lAi, pg_b);
    scan_a<<<BB*NC, SS>>>();
    scan_b<<<1, BB*SS>>>();
    scan_c<<<BB*NC, SS>>>(out);
    gemm2<<<(MM/128)*32, 256, SMEM_BYTES>>>(x, Dp, out);
}